// round 13
// baseline (speedup 1.0000x reference)
#include <cuda_runtime.h>
#include <cstdint>

// TVConv: per-pixel spatially-varying 3x3 depthwise conv, zero padding.
// x:           (B=8, C=96, H=128, W=128) fp32
// weight_maps: (1,   C=96, 3, 3, H, W)   fp32  (batch-invariant)
// out:         (B, C, H, W) fp32
//
// R9/R10 lesson: deeper load-prefetch doesn't help -> the residual stall
// is the SHFL halo exchange (6 x ~28cyc serial, unprefetchable, fed by
// the just-arrived load). R11 = R7 with SHFLs replaced by direct scalar
// halo loads (xrow[w0-1], xrow[w0+4]) — same 128B lines as the warp's
// float4 load (L1 sector hits), issued at iteration top so the distance-1
// prefetch covers them. Per iter: 9 LDG + 0 SHFL (was 4 LDG + 6 SHFL).
// Keep: 4px/thread, warp==row, register weights (__ldcs), __stcs out,
// distance-1 prefetch, lb(256,3).

namespace {
constexpr int B = 8;
constexpr int C = 96;
constexpr int H = 128;
constexpr int W = 128;
constexpr int HW = H * W;
constexpr unsigned CHW = (unsigned)C * HW;
constexpr int THREADS = 256;
constexpr int NBLOCKS = C * H * (W / 4) / THREADS;  // 1536
}

__device__ __forceinline__ float4 ldg4(const float* p) {
    return *reinterpret_cast<const float4*>(p);
}

// One input row: aligned float4 + two scalar halos, all plain loads.
struct Row {
    float4 r;
    float lf, rt;
};

__device__ __forceinline__ Row load_row(const float* xrow, int w0) {
    Row o;
    o.r  = ldg4(xrow + w0);
    o.lf = (w0 > 0)     ? __ldg(xrow + w0 - 1) : 0.f;   // w = -1 pad
    o.rt = (w0 < W - 4) ? __ldg(xrow + w0 + 4) : 0.f;   // w = 128 pad
    return o;
}

__device__ __forceinline__ void accum_row(
    const Row& v, float4 k0, float4 k1, float4 k2,
    float& a0, float& a1, float& a2, float& a3)
{
    a0 = fmaf(k0.x, v.lf,  fmaf(k1.x, v.r.x, fmaf(k2.x, v.r.y, a0)));
    a1 = fmaf(k0.y, v.r.x, fmaf(k1.y, v.r.y, fmaf(k2.y, v.r.z, a1)));
    a2 = fmaf(k0.z, v.r.y, fmaf(k1.z, v.r.z, fmaf(k2.z, v.r.w, a2)));
    a3 = fmaf(k0.w, v.r.z, fmaf(k1.w, v.r.w, fmaf(k2.w, v.rt,  a3)));
}

__global__ __launch_bounds__(THREADS, 3) void tvconv_kernel(
    const float* __restrict__ x,
    const float* __restrict__ wm,
    float* __restrict__ out)
{
    int idx  = blockIdx.x * THREADS + threadIdx.x;
    int lane = threadIdx.x & 31;       // == w4 (W/4 == 32)
    int t    = idx >> 5;
    int h    = t % H;
    int c    = t / H;
    int w0   = lane * 4;

    // ---- 9 weight taps, register-resident, streaming (read-once) ----
    const float* wbase = wm + (unsigned)c * 9u * HW + (unsigned)h * W + w0;
    float4 wt[9];
#pragma unroll
    for (int k = 0; k < 9; k++)
        wt[k] = __ldcs(reinterpret_cast<const float4*>(wbase + (unsigned)k * HW));

    const unsigned rowbase = (unsigned)c * HW + (unsigned)h * W;
    const bool has_up = (h > 0), has_dn = (h < H - 1);
    const Row zrow = {make_float4(0.f, 0.f, 0.f, 0.f), 0.f, 0.f};

    // prime batch 0
    const float* xp = x + rowbase;
    Row c1 = load_row(xp, w0);
    Row c0 = has_up ? load_row(xp - W, w0) : zrow;
    Row c2 = has_dn ? load_row(xp + W, w0) : zrow;

#pragma unroll
    for (int b = 0; b < B; b++) {
        Row n0 = zrow, n1 = zrow, n2 = zrow;
        if (b + 1 < B) {               // distance-1 prefetch of next batch
            const float* xn = x + (unsigned)(b + 1) * CHW + rowbase;
            n1 = load_row(xn, w0);
            n0 = has_up ? load_row(xn - W, w0) : zrow;
            n2 = has_dn ? load_row(xn + W, w0) : zrow;
        }

        float a0 = 0.f, a1 = 0.f, a2 = 0.f, a3 = 0.f;
        accum_row(c0, wt[0], wt[1], wt[2], a0, a1, a2, a3);
        accum_row(c1, wt[3], wt[4], wt[5], a0, a1, a2, a3);
        accum_row(c2, wt[6], wt[7], wt[8], a0, a1, a2, a3);

        __stcs(reinterpret_cast<float4*>(
                   out + (unsigned)b * CHW + rowbase + w0),
               make_float4(a0, a1, a2, a3));

        c0 = n0; c1 = n1; c2 = n2;
    }
}

extern "C" void kernel_launch(void* const* d_in, const int* in_sizes, int n_in,
                              void* d_out, int out_size)
{
    const float* x  = (const float*)d_in[0];
    const float* wm = (const float*)d_in[1];
    float* out      = (float*)d_out;

    tvconv_kernel<<<NBLOCKS, THREADS>>>(x, wm, out);
}

// round 14
// speedup vs baseline: 1.3561x; 1.3561x over previous
#include <cuda_runtime.h>
#include <cstdint>

// TVConv: per-pixel spatially-varying 3x3 depthwise conv, zero padding.
// x:           (B=8, C=96, H=128, W=128) fp32
// weight_maps: (1,   C=96, 3, 3, H, W)   fp32  (batch-invariant)
// out:         (B, C, H, W) fp32
//
// R13: LOOP INVERSION. Outer loop = tap row (3 iters), inner = batch (8).
// All 8 batches accumulate in registers (8 x float4 = 32 regs); only ONE
// tap row's weights (12 regs) is live at a time instead of all 36.
// Peak regs ~62 -> lb(256,4) -> 42.6% occupancy WITH R7's per-iteration
// efficiency (same 24 x-loads, 9 weight loads, 48 shfls, 8 stores; the 8
// inner-loop loads are independent -> MLP 8 without prefetch machinery).
// R11 lesson kept: halos via SHFL (scalar halo loads blow up L1).

namespace {
constexpr int B = 8;
constexpr int C = 96;
constexpr int H = 128;
constexpr int W = 128;
constexpr int HW = H * W;
constexpr unsigned CHW = (unsigned)C * HW;          // batch stride
constexpr int THREADS = 256;
constexpr int NBLOCKS = C * H * (W / 4) / THREADS;  // 1536
}

__device__ __forceinline__ float4 ldg4(const float* p) {
    return *reinterpret_cast<const float4*>(p);
}

__global__ __launch_bounds__(THREADS, 4) void tvconv_kernel(
    const float* __restrict__ x,
    const float* __restrict__ wm,
    float* __restrict__ out)
{
    int idx  = blockIdx.x * THREADS + threadIdx.x;
    int lane = threadIdx.x & 31;       // == w4 (W/4 == 32)
    int t    = idx >> 5;
    int h    = t % H;
    int c    = t / H;
    int w0   = lane * 4;

    const unsigned rowoff = (unsigned)h * W + w0;

    float4 acc[B];
#pragma unroll
    for (int b = 0; b < B; b++) acc[b] = make_float4(0.f, 0.f, 0.f, 0.f);

#pragma unroll
    for (int i = 0; i < 3; i++) {
        int hh = h + i - 1;
        if ((unsigned)hh >= (unsigned)H) continue;   // warp-uniform (h uniform)

        // one tap-row's weights: 3 float4 = 12 regs, loaded once, streaming
        const float* wrow = wm + (unsigned)c * 9u * HW
                               + (unsigned)(3 * i) * HW + rowoff;
        float4 k0 = __ldcs(reinterpret_cast<const float4*>(wrow));
        float4 k1 = __ldcs(reinterpret_cast<const float4*>(wrow + HW));
        float4 k2 = __ldcs(reinterpret_cast<const float4*>(wrow + 2 * HW));

        const float* xr = x + (unsigned)c * HW + (unsigned)hh * W + w0;

#pragma unroll
        for (int b = 0; b < B; b++) {
            float4 r = ldg4(xr + (unsigned)b * CHW);
            float lf = __shfl_up_sync(0xffffffffu,  r.w, 1);
            float rt = __shfl_down_sync(0xffffffffu, r.x, 1);
            if (lane == 0)  lf = 0.f;   // w = -1  pad
            if (lane == 31) rt = 0.f;   // w = 128 pad

            acc[b].x = fmaf(k0.x, lf,  fmaf(k1.x, r.x, fmaf(k2.x, r.y, acc[b].x)));
            acc[b].y = fmaf(k0.y, r.x, fmaf(k1.y, r.y, fmaf(k2.y, r.z, acc[b].y)));
            acc[b].z = fmaf(k0.z, r.y, fmaf(k1.z, r.z, fmaf(k2.z, r.w, acc[b].z)));
            acc[b].w = fmaf(k0.w, r.z, fmaf(k1.w, r.w, fmaf(k2.w, rt,  acc[b].w)));
        }
    }

    const unsigned obase = (unsigned)c * HW + rowoff;
#pragma unroll
    for (int b = 0; b < B; b++)
        __stcs(reinterpret_cast<float4*>(out + (unsigned)b * CHW + obase),
               acc[b]);
}

extern "C" void kernel_launch(void* const* d_in, const int* in_sizes, int n_in,
                              void* d_out, int out_size)
{
    const float* x  = (const float*)d_in[0];
    const float* wm = (const float*)d_in[1];
    float* out      = (float*)d_out;

    tvconv_kernel<<<NBLOCKS, THREADS>>>(x, wm, out);
}